// round 10
// baseline (speedup 1.0000x reference)
#include <cuda_runtime.h>
#include <cuda_bf16.h>
#include <math.h>
#include <stdint.h>

// Problem constants
#define BBATCH 32
#define NLABEL 8192
#define MROWS 32768
#define EPS_ 1e-12f

#define SCALE_ACT 16.f
#define SCALE_W 512.f
#define INV_SCALE (1.f / 8192.f)

// ---------------- device scratch ----------------
__device__ int8_t g_e8[(size_t)MROWS * 1024];
__device__ int8_t g_h18[(size_t)MROWS * 2048];
__device__ __nv_bfloat16 g_ek16[(size_t)MROWS * 1024];
__device__ float g_w2f[2048 * 1024];
__device__ float g_b2f[1024];
__device__ int8_t g_w1t8[2048 * 1024];
__device__ int8_t g_w2t8[1024 * 2048];
__device__ float g_qv[512 * 64];
__device__ float g_sqq[512];

// ---------------- PTX helpers ----------------
__device__ __forceinline__ uint32_t smem_u32(const void* p) {
    uint32_t a;
    asm("{ .reg .u64 t; cvta.to.shared.u64 t, %1; cvt.u32.u64 %0, t; }" : "=r"(a) : "l"(p));
    return a;
}
__device__ __forceinline__ void cpa16(uint32_t saddr, const void* g) {
    asm volatile("cp.async.cg.shared.global [%0], [%1], 16;" :: "r"(saddr), "l"(g));
}
#define CP_COMMIT() asm volatile("cp.async.commit_group;" ::: "memory")

#define LDSM4(r0, r1, r2, r3, addr) \
    asm volatile("ldmatrix.sync.aligned.m8n8.x4.shared.b16 {%0,%1,%2,%3}, [%4];" \
                 : "=r"(r0), "=r"(r1), "=r"(r2), "=r"(r3) : "r"(addr))

// INT8 IMMA: m16n8k32, s32 accum (native legacy tensor path, sm_75+)
#define MMA16832I(c, a0, a1, a2, a3, b0, b1) \
    asm volatile( \
        "mma.sync.aligned.m16n8k32.row.col.s32.s8.s8.s32 " \
        "{%0,%1,%2,%3}, {%4,%5,%6,%7}, {%8,%9}, {%0,%1,%2,%3};" \
        : "+r"((c)[0]), "+r"((c)[1]), "+r"((c)[2]), "+r"((c)[3]) \
        : "r"(a0), "r"(a1), "r"(a2), "r"(a3), "r"(b0), "r"(b1))

__device__ __forceinline__ int8_t f2s8(float x) {
    int q = __float2int_rn(x);
    q = q > 127 ? 127 : (q < -127 ? -127 : q);
    return (int8_t)q;
}

// ---------------- weight folding ----------------
__global__ void fold_w2_kernel(const float* __restrict__ tc_w2,
                               const float* __restrict__ hyp_w) {
    __shared__ float hw[64 * 64];
    __shared__ float row[1024];
    int k = blockIdx.x;
    int tid = threadIdx.x;
    for (int i = tid; i < 4096; i += 256) hw[i] = hyp_w[i];
    for (int i = tid; i < 1024; i += 256) row[i] = tc_w2[(size_t)k * 1024 + i];
    __syncthreads();
#pragma unroll
    for (int t = 0; t < 4; t++) {
        int c = tid + t * 256;
        int j = c >> 6, dp = c & 63;
        float a0 = 0.f, a1 = 0.f;
#pragma unroll 8
        for (int d = 0; d < 64; d += 2) {
            a0 += row[j * 64 + d] * hw[d * 64 + dp];
            a1 += row[j * 64 + d + 1] * hw[(d + 1) * 64 + dp];
        }
        g_w2f[(size_t)k * 1024 + c] = a0 + a1;
    }
}

__global__ void fold_b2_kernel(const float* __restrict__ tc_b2,
                               const float* __restrict__ hyp_w,
                               const float* __restrict__ hyp_b) {
    int c = blockIdx.x * 256 + threadIdx.x;
    if (c < 1024) {
        int j = c >> 6, dp = c & 63;
        float acc = hyp_b[dp];
        for (int d = 0; d < 64; d++) acc += tc_b2[j * 64 + d] * hyp_w[d * 64 + dp];
        g_b2f[c] = acc;
    }
}

// ---------------- fp32 -> int8 convert (x SCALE_ACT) ----------------
__global__ __launch_bounds__(256) void cvt_s8_kernel(const float* __restrict__ in,
                                                     int8_t* __restrict__ out, int n8) {
    int i = blockIdx.x * 256 + threadIdx.x;
    if (i < n8) {
        float4 v0 = ((const float4*)in)[2 * i];
        float4 v1 = ((const float4*)in)[2 * i + 1];
        uint32_t lo = (uint32_t)(uint8_t)f2s8(v0.x * SCALE_ACT) |
                      ((uint32_t)(uint8_t)f2s8(v0.y * SCALE_ACT) << 8) |
                      ((uint32_t)(uint8_t)f2s8(v0.z * SCALE_ACT) << 16) |
                      ((uint32_t)(uint8_t)f2s8(v0.w * SCALE_ACT) << 24);
        uint32_t hi = (uint32_t)(uint8_t)f2s8(v1.x * SCALE_ACT) |
                      ((uint32_t)(uint8_t)f2s8(v1.y * SCALE_ACT) << 8) |
                      ((uint32_t)(uint8_t)f2s8(v1.z * SCALE_ACT) << 16) |
                      ((uint32_t)(uint8_t)f2s8(v1.w * SCALE_ACT) << 24);
        ((uint2*)out)[i] = make_uint2(lo, hi);
    }
}

// ---------------- transpose fp32 -> int8 (x SCALE_W) ----------------
__global__ void transpose_cvt_s8_kernel(const float* __restrict__ in,
                                        int8_t* __restrict__ out, int R, int C) {
    __shared__ float t[32][33];
    int cb = blockIdx.x * 32, rb = blockIdx.y * 32;
    int x = threadIdx.x, y = threadIdx.y;
#pragma unroll
    for (int i = y; i < 32; i += 8) t[i][x] = in[(size_t)(rb + i) * C + cb + x];
    __syncthreads();
#pragma unroll
    for (int i = y; i < 32; i += 8)
        out[(size_t)(cb + i) * R + rb + x] = f2s8(t[x][i] * SCALE_W);
}

// ---------------- int8 IMMA GEMM, 128x256 CTA / 64x64 warp -------------------
// C[M,N] = A[M,K](s8,xSA) @ B[N,K]^T(s8,xSW) + bias, acc descaled by 1/8192
// EPI=0: relu -> int8 (xSCALE_ACT);  EPI=1: expmap0 -> bf16 (register-only)
#define STG 49152
#define NSTG 4

template <int EPI>
__global__ __launch_bounds__(256, 1) void gemm_s8_kernel(
    const int8_t* __restrict__ A, const int8_t* __restrict__ B,
    const float* __restrict__ bias, int8_t* __restrict__ C8,
    __nv_bfloat16* __restrict__ Cb, int M, int N, int K) {
    extern __shared__ char dsm[];
    __shared__ float sbias[256];

    const int tid = threadIdx.x;
    const int wid = tid >> 5, lane = tid & 31;
    const int wm = wid & 1;        // m half (64 rows)
    const int wn = wid >> 1;       // n quarter (64 cols)
    const int n0 = blockIdx.x * 256;
    const int m0 = blockIdx.y * 128;
    const uint32_t sb = smem_u32(dsm);

    sbias[tid] = bias[n0 + tid];

    const int g = lane >> 3, rin = lane & 7;
    const uint32_t laneA = (uint32_t)((g & 1) * 1024 + (g >> 1) * 128 + rin * 16);
    const uint32_t laneB = (uint32_t)((g >> 1) * 1024 + (g & 1) * 128 + rin * 16);

    int acc[4][8][4];
#pragma unroll
    for (int i = 0; i < 4; i++)
#pragma unroll
        for (int n = 0; n < 8; n++)
#pragma unroll
            for (int r = 0; r < 4; r++) acc[i][n][r] = 0;

    const int nchunk = K >> 7;   // 128 int8 per chunk

    auto load_stage = [&](int buf, int kc) {
        const uint32_t sbase = sb + buf * STG;
#pragma unroll
        for (int it = 0; it < 12; it++) {
            int uid = tid + it * 256;
            if (uid < 1024) {
                int rg = uid >> 6, seg = (uid >> 3) & 7, rr = uid & 7;
                cpa16(sbase + uid * 16,
                      A + (size_t)(m0 + rg * 8 + rr) * K + kc * 128 + seg * 16);
            } else {
                int u = uid - 1024;
                int rg = u >> 6, seg = (u >> 3) & 7, rr = u & 7;
                cpa16(sbase + 16384 + u * 16,
                      B + (size_t)(n0 + rg * 8 + rr) * K + kc * 128 + seg * 16);
            }
        }
        CP_COMMIT();
    };

    load_stage(0, 0);
    if (nchunk > 1) load_stage(1, 1); else CP_COMMIT();
    if (nchunk > 2) load_stage(2, 2); else CP_COMMIT();

    for (int kc = 0; kc < nchunk; kc++) {
        asm volatile("cp.async.wait_group 2;" ::: "memory");
        __syncthreads();
        if (kc + 3 < nchunk) load_stage((kc + 3) & 3, kc + 3);
        else CP_COMMIT();

        const int buf = kc & 3;
        const uint32_t tA = sb + buf * STG + (uint32_t)wm * 8192;
        const uint32_t tB = sb + buf * STG + 16384 + (uint32_t)wn * 8192;

#pragma unroll
        for (int j = 0; j < 4; j++) {          // each j = k32 int8 (32 bytes)
            uint32_t a[16], b[16];
            const uint32_t jo = (uint32_t)j * 256;
#pragma unroll
            for (int i = 0; i < 4; i++)
                LDSM4(a[4 * i], a[4 * i + 1], a[4 * i + 2], a[4 * i + 3],
                      tA + (uint32_t)i * 2048 + jo + laneA);
#pragma unroll
            for (int p = 0; p < 4; p++)
                LDSM4(b[4 * p], b[4 * p + 1], b[4 * p + 2], b[4 * p + 3],
                      tB + (uint32_t)p * 2048 + jo + laneB);
#pragma unroll
            for (int i = 0; i < 4; i++)
#pragma unroll
                for (int n = 0; n < 8; n++)
                    MMA16832I(acc[i][n], a[4 * i], a[4 * i + 1], a[4 * i + 2], a[4 * i + 3],
                              b[(n >> 1) * 4 + (n & 1) * 2], b[(n >> 1) * 4 + (n & 1) * 2 + 1]);
        }
    }
    asm volatile("cp.async.wait_group 0;" ::: "memory");
    __syncthreads();

    // ---------------- epilogue ----------------
    if (EPI == 0) {
        // relu -> int8 (x SCALE_ACT), staged in SMEM [128][272B]
        uint8_t* sh = (uint8_t*)dsm;
#pragma unroll
        for (int i = 0; i < 4; i++) {
#pragma unroll
            for (int half = 0; half < 2; half++) {
                const int row = 64 * wm + 16 * i + 8 * half + (lane >> 2);
#pragma unroll
                for (int n = 0; n < 8; n++) {
                    const int col = 64 * wn + 8 * n + (lane & 3) * 2;
                    float v0 = fmaxf((float)acc[i][n][2 * half] * INV_SCALE + sbias[col], 0.f);
                    float v1 =
                        fmaxf((float)acc[i][n][2 * half + 1] * INV_SCALE + sbias[col + 1], 0.f);
                    uint16_t pk = (uint16_t)(uint8_t)f2s8(v0 * SCALE_ACT) |
                                  ((uint16_t)(uint8_t)f2s8(v1 * SCALE_ACT) << 8);
                    *(uint16_t*)(sh + row * 272 + col) = pk;
                }
            }
        }
        __syncthreads();
#pragma unroll
        for (int it = 0; it < 8; it++) {
            int idx = tid + it * 256;          // 2048 uint4 (128 rows x 256B)
            int row = idx >> 4, seg = idx & 15;
            uint4 v = *(const uint4*)(sh + row * 272 + seg * 16);
            *(uint4*)(C8 + (size_t)(m0 + row) * N + n0 + seg * 16) = v;
        }
    } else {
        // fused expmap0, register-only, bf16 output
#pragma unroll
        for (int i = 0; i < 4; i++) {
#pragma unroll
            for (int half = 0; half < 2; half++) {
                const int row = m0 + 64 * wm + 16 * i + 8 * half + (lane >> 2);
                float v[8][2];
                float p = 0.f;
#pragma unroll
                for (int n = 0; n < 8; n++) {
                    const int col = 64 * wn + 8 * n + (lane & 3) * 2;
                    v[n][0] = (float)acc[i][n][2 * half] * INV_SCALE + sbias[col];
                    v[n][1] = (float)acc[i][n][2 * half + 1] * INV_SCALE + sbias[col + 1];
                    p += v[n][0] * v[n][0] + v[n][1] * v[n][1];
                }
                p += __shfl_xor_sync(0xffffffffu, p, 1);
                p += __shfl_xor_sync(0xffffffffu, p, 2);
                float nrm = sqrtf(fmaxf(p, EPS_));
                float s = tanhf(nrm) / nrm;
                __nv_bfloat16* dst = Cb + (size_t)row * N + n0 + 64 * wn + (lane & 3) * 2;
#pragma unroll
                for (int n = 0; n < 8; n++) {
                    *(uint32_t*)(dst + 8 * n) =
                        ((uint32_t)__bfloat16_as_ushort(__float2bfloat16(v[n][1] * s)) << 16) |
                        __bfloat16_as_ushort(__float2bfloat16(v[n][0] * s));
                }
            }
        }
    }
}

// ---------------- hyperbolic path search: one CTA per (b, head) -------------
__global__ __launch_bounds__(256, 1) void attn_kernel(const __nv_bfloat16* __restrict__ ek16,
                                                      const float* __restrict__ label,
                                                      const int* __restrict__ y,
                                                      const int* __restrict__ mask_text) {
    extern __shared__ uint32_t skeys[];            // [1024 * 33] bf16x2 words
    __shared__ float2 scf[1024];
    __shared__ int msk[1024];
    __shared__ __align__(16) float q_s[64];
    __shared__ float sq_q_s, fac_s;
    __shared__ float wmx[8], wd_s[8];
    __shared__ float wacc[8][64];

    const int bh = blockIdx.x;
    const int b = bh >> 4;
    const int hh = bh & 15;
    const int tid = threadIdx.x;
    const int w = tid >> 5;
    const int lane = tid & 31;

    const __nv_bfloat16* ekb = ek16 + ((size_t)b * 1024 + hh * 64) * 1024;

#pragma unroll 4
    for (int t = 0; t < 128; t++) {
        const int idx = w * 128 + t;
        uint32_t kw = *(const uint32_t*)(ekb + (size_t)(idx >> 4) * 1024 + (idx & 15) * 64 + lane * 2);
        skeys[idx * 33 + lane] = kw;
    }
    for (int i = tid; i < 1024; i += 256) msk[i] = mask_text[b * 1024 + i];
    if (tid < 64) q_s[tid] = label[(size_t)y[b] * 64 + tid];
    __syncthreads();

#pragma unroll
    for (int i = 0; i < 4; i++) {
        const int idx = tid + i * 256;
        float ps = 0.f;
#pragma unroll
        for (int wd = 0; wd < 32; wd++) {
            uint32_t kw = skeys[idx * 33 + wd];
            __nv_bfloat162 h2 = *(__nv_bfloat162*)&kw;
            float k0 = __bfloat162float(h2.x), k1 = __bfloat162float(h2.y);
            ps += k0 * k0 + k1 * k1;
        }
        float idk = 1.f / fmaxf(1.f - ps, EPS_);
        scf[idx] = make_float2((1.f + ps) * idk, 2.f * idk);
    }
    if (w == 0) {
        float2 qv = *(float2*)(q_s + lane * 2);
        float p = qv.x * qv.x + qv.y * qv.y;
#pragma unroll
        for (int off = 16; off; off >>= 1) p += __shfl_xor_sync(0xffffffffu, p, off);
        if (lane == 0) sq_q_s = p;
    }
    __syncthreads();

    for (int layer = 0; layer < 4; layer++) {
        const float sqq = sq_q_s;
        const float aq = 1.f + sqq;
        const float idq = 1.f / fmaxf(1.f - sqq, EPS_);

        float sc[4], cfv[4], cnv[4];
#pragma unroll
        for (int i = 0; i < 4; i++) {
            const int idx = w * 128 + i * 32 + lane;
            const uint32_t* kp = skeys + idx * 33;
            float dot = 0.f;
#pragma unroll
            for (int wd = 0; wd < 32; wd++) {
                uint32_t kw = kp[wd];
                float2 qv = *(float2*)(q_s + 2 * wd);
                __nv_bfloat162 h2 = *(__nv_bfloat162*)&kw;
                dot += __bfloat162float(h2.x) * qv.x + __bfloat162float(h2.y) * qv.y;
            }
            float2 c = scf[idx];
            cfv[i] = c.x;
            cnv[i] = c.y;
            float x = (aq * c.x - 2.f * dot * c.y) * idq;
            float tt = fmaxf(x - 1.f, 1e-6f);
            float s = -log1pf(tt + sqrtf(tt * (tt + 2.f)));
            sc[i] = msk[idx] ? s : -1e9f;
        }
        float m = fmaxf(fmaxf(sc[0], sc[1]), fmaxf(sc[2], sc[3]));
        float wgt[4];
        float den = 0.f;
#pragma unroll
        for (int i = 0; i < 4; i++) {
            float e = __expf(sc[i] - m);
            den += e * cfv[i];
            wgt[i] = e * cnv[i];
        }

        float acc[64];
#pragma unroll
        for (int wd = 0; wd < 32; wd++) {
            float a0 = 0.f, a1 = 0.f;
#pragma unroll
            for (int i = 0; i < 4; i++) {
                uint32_t kw = skeys[(w * 128 + i * 32 + lane) * 33 + wd];
                __nv_bfloat162 h2 = *(__nv_bfloat162*)&kw;
                a0 += wgt[i] * __bfloat162float(h2.x);
                a1 += wgt[i] * __bfloat162float(h2.y);
            }
            acc[2 * wd] = a0;
            acc[2 * wd + 1] = a1;
        }

        float mw = m;
#pragma unroll
        for (int off = 16; off; off >>= 1) mw = fmaxf(mw, __shfl_xor_sync(0xffffffffu, mw, off));
        float s = __expf(m - mw);
        den *= s;
#pragma unroll
        for (int d = 0; d < 64; d++) acc[d] *= s;
#pragma unroll
        for (int off = 16; off; off >>= 1) {
            den += __shfl_xor_sync(0xffffffffu, den, off);
#pragma unroll
            for (int d = 0; d < 64; d++) acc[d] += __shfl_xor_sync(0xffffffffu, acc[d], off);
        }
        if (lane == 0) {
            wmx[w] = mw;
            wd_s[w] = den;
#pragma unroll
            for (int d = 0; d < 64; d++) wacc[w][d] = acc[d];
        }
        __syncthreads();

        if (tid < 64) {
            float M = wmx[0];
#pragma unroll
            for (int ww = 1; ww < 8; ww++) M = fmaxf(M, wmx[ww]);
            float num = 0.f, D = 0.f;
#pragma unroll
            for (int ww = 0; ww < 8; ww++) {
                float al = __expf(wmx[ww] - M);
                num += al * wacc[ww][tid];
                D += al * wd_s[ww];
            }
            q_s[tid] = num / D;
        }
        __syncthreads();
        if (w == 0) {
            float2 mv = *(float2*)(q_s + lane * 2);
            float p = mv.x * mv.x + mv.y * mv.y;
#pragma unroll
            for (int off = 16; off; off >>= 1) p += __shfl_xor_sync(0xffffffffu, p, off);
            if (lane == 0) {
                float r = 1.f / (1.f + sqrtf(fmaxf(1.f - p, EPS_)));
                fac_s = r;
                sq_q_s = p * r * r;
            }
        }
        __syncthreads();
        if (tid < 64) q_s[tid] *= fac_s;
        __syncthreads();
    }
    if (tid < 64) g_qv[(size_t)bh * 64 + tid] = q_s[tid];
    if (tid == 0) g_sqq[bh] = sq_q_s;
}

// ---------------- label distances + aggregator MLP --------------------------
__global__ __launch_bounds__(128) void label_mlp_kernel(
    const float* __restrict__ label,
    const float* __restrict__ w1, const float* __restrict__ b1,
    const float* __restrict__ w2, const float* __restrict__ b2,
    const float* __restrict__ w3, const float* __restrict__ b3,
    const float* __restrict__ w4, const float* __restrict__ b4,
    const int* __restrict__ mask_label, float* __restrict__ out) {
    __shared__ float lab[128][65];
    __shared__ float qs[16 * 64];
    __shared__ float P[16], Qc[16];
    __shared__ float sw1[512], sb1[32], sw2[1024], sb2[32], sw3[512], sb3[16], sw4[16], sb4s[1];

    const int b = blockIdx.y;
    const int base = blockIdx.x * 128;
    const int tid = threadIdx.x;

    for (int i = tid; i < 128 * 64; i += 128) lab[i >> 6][i & 63] = label[(size_t)base * 64 + i];
    for (int i = tid; i < 1024; i += 128) qs[i] = g_qv[(size_t)b * 1024 + i];
    if (tid < 16) {
        float s = g_sqq[b * 16 + tid];
        float inv = 1.f / fmaxf(1.f - s, EPS_);
        P[tid] = (1.f + s) * inv;
        Qc[tid] = 4.f * inv;
    }
    for (int i = tid; i < 512; i += 128) sw1[i] = w1[i];
    for (int i = tid; i < 1024; i += 128) sw2[i] = w2[i];
    for (int i = tid; i < 512; i += 128) sw3[i] = w3[i];
    if (tid < 32) { sb1[tid] = b1[tid]; sb2[tid] = b2[tid]; }
    if (tid < 16) { sb3[tid] = b3[tid]; sw4[tid] = w4[tid]; }
    if (tid == 0) sb4s[0] = b4[0];
    __syncthreads();

    float sq_l = 0.f;
#pragma unroll 8
    for (int d = 0; d < 64; d++) { float v = lab[tid][d]; sq_l += v * v; }
    const float invl = 1.f / fmaxf(1.f - sq_l, EPS_);
    const float L1 = (1.f + sq_l) * invl;

    float dh[16];
#pragma unroll
    for (int h = 0; h < 16; h++) {
        float dot = 0.f;
#pragma unroll 8
        for (int d = 0; d < 64; d++) dot += qs[h * 64 + d] * lab[tid][d];
        float x = P[h] * L1 - Qc[h] * invl * dot;
        float tt = fmaxf(x - 1.f, 1e-6f);
        dh[h] = log1pf(tt + sqrtf(tt * (tt + 2.f)));
    }
    float x1[32];
#pragma unroll
    for (int j = 0; j < 32; j++) {
        float a = sb1[j];
#pragma unroll
        for (int h = 0; h < 16; h++) a += dh[h] * sw1[h * 32 + j];
        x1[j] = fmaxf(a, 0.f);
    }
    float x2[32];
#pragma unroll
    for (int j = 0; j < 32; j++) {
        float a = sb2[j];
#pragma unroll
        for (int i = 0; i < 32; i++) a += x1[i] * sw2[i * 32 + j];
        x2[j] = fmaxf(a, 0.f);
    }
    float x3[16];
#pragma unroll
    for (int j = 0; j < 16; j++) {
        float a = sb3[j];
#pragma unroll
        for (int i = 0; i < 32; i++) a += x2[i] * sw3[i * 16 + j];
        x3[j] = fmaxf(a, 0.f);
    }
    float val = sb4s[0];
#pragma unroll
    for (int h = 0; h < 16; h++) val += x3[h] * sw4[h];

    const int n = base + tid;
    out[(size_t)b * NLABEL + n] = (mask_label[(size_t)b * NLABEL + n] > 0) ? val : -500.f;
}

// ---------------- launch -----------------------------------------------------
extern "C" void kernel_launch(void* const* d_in, const int* in_sizes, int n_in,
                              void* d_out, int out_size) {
    const float* e = (const float*)d_in[0];
    const float* label = (const float*)d_in[1];
    const float* tc_w1 = (const float*)d_in[2];
    const float* tc_b1 = (const float*)d_in[3];
    const float* tc_w2 = (const float*)d_in[4];
    const float* tc_b2 = (const float*)d_in[5];
    const float* hyp_w = (const float*)d_in[6];
    const float* hyp_b = (const float*)d_in[7];
    const float* aw1 = (const float*)d_in[8];
    const float* ab1 = (const float*)d_in[9];
    const float* aw2 = (const float*)d_in[10];
    const float* ab2 = (const float*)d_in[11];
    const float* aw3 = (const float*)d_in[12];
    const float* ab3 = (const float*)d_in[13];
    const float* aw4 = (const float*)d_in[14];
    const float* ab4 = (const float*)d_in[15];
    const int* y = (const int*)d_in[16];
    const int* mt = (const int*)d_in[17];
    const int* ml = (const int*)d_in[18];
    float* out = (float*)d_out;

    int8_t *e8, *h18, *w1t8, *w2t8;
    __nv_bfloat16* ek16;
    float *w2fp, *b2fp;
    cudaGetSymbolAddress((void**)&e8, g_e8);
    cudaGetSymbolAddress((void**)&h18, g_h18);
    cudaGetSymbolAddress((void**)&w1t8, g_w1t8);
    cudaGetSymbolAddress((void**)&w2t8, g_w2t8);
    cudaGetSymbolAddress((void**)&ek16, g_ek16);
    cudaGetSymbolAddress((void**)&w2fp, g_w2f);
    cudaGetSymbolAddress((void**)&b2fp, g_b2f);

    const int smem_bytes = NSTG * STG;   // 192KB
    cudaFuncSetAttribute(gemm_s8_kernel<0>, cudaFuncAttributeMaxDynamicSharedMemorySize,
                         smem_bytes);
    cudaFuncSetAttribute(gemm_s8_kernel<1>, cudaFuncAttributeMaxDynamicSharedMemorySize,
                         smem_bytes);
    const int attn_smem = 1024 * 33 * 4;  // 132KB
    cudaFuncSetAttribute(attn_kernel, cudaFuncAttributeMaxDynamicSharedMemorySize, attn_smem);

    // launch order: gemm1 in profiler slot #4
    cvt_s8_kernel<<<(MROWS * 1024 / 8 + 255) / 256, 256>>>(e, e8, MROWS * 1024 / 8);
    transpose_cvt_s8_kernel<<<dim3(2048 / 32, 1024 / 32), dim3(32, 8)>>>(tc_w1, w1t8, 1024, 2048);
    fold_w2_kernel<<<2048, 256>>>(tc_w2, hyp_w);

    // GEMM1 (launch #4): h1 = relu(e @ w1 + b1) -> int8
    gemm_s8_kernel<0><<<dim3(8, 256), 256, smem_bytes>>>(
        e8, w1t8, tc_b1, h18, nullptr, MROWS, 2048, 1024);

    fold_b2_kernel<<<4, 256>>>(tc_b2, hyp_w, hyp_b);
    transpose_cvt_s8_kernel<<<dim3(1024 / 32, 2048 / 32), dim3(32, 8)>>>(w2fp, w2t8, 2048, 1024);

    // GEMM2: ek = expmap0(h1 @ w2f + b2f) -> bf16
    gemm_s8_kernel<1><<<dim3(4, 256), 256, smem_bytes>>>(
        h18, w2t8, b2fp, nullptr, ek16, MROWS, 1024, 2048);

    attn_kernel<<<512, 256, attn_smem>>>(ek16, label, y, mt);
    label_mlp_kernel<<<dim3(NLABEL / 128, BBATCH), 128>>>(label, aw1, ab1, aw2, ab2,
                                                          aw3, ab3, aw4, ab4, ml, out);
}

// round 11
// speedup vs baseline: 1.9472x; 1.9472x over previous
#include <cuda_runtime.h>
#include <cuda_bf16.h>
#include <cuda_fp8.h>
#include <cuda_fp16.h>
#include <math.h>
#include <stdint.h>

// Problem constants
#define BBATCH 32
#define NLABEL 8192
#define MROWS 32768
#define EPS_ 1e-12f

#define SCALE_ACT 16.f
#define SCALE_W 64.f
#define INV_SCALE (1.f / 1024.f)

// ---------------- device scratch ----------------
__device__ uint8_t g_e8[(size_t)MROWS * 1024];
__device__ uint8_t g_h18[(size_t)MROWS * 2048];
__device__ __nv_bfloat16 g_ek16[(size_t)MROWS * 1024];
__device__ float g_w2f[2048 * 1024];
__device__ float g_b2f[1024];
__device__ uint8_t g_w1t8[2048 * 1024];
__device__ uint8_t g_w2t8[1024 * 2048];
__device__ float g_qv[512 * 64];
__device__ float g_sqq[512];

// ---------------- PTX helpers ----------------
__device__ __forceinline__ uint32_t smem_u32(const void* p) {
    uint32_t a;
    asm("{ .reg .u64 t; cvta.to.shared.u64 t, %1; cvt.u32.u64 %0, t; }" : "=r"(a) : "l"(p));
    return a;
}
__device__ __forceinline__ void cpa16(uint32_t saddr, const void* g) {
    asm volatile("cp.async.cg.shared.global [%0], [%1], 16;" :: "r"(saddr), "l"(g));
}
#define CP_COMMIT() asm volatile("cp.async.commit_group;" ::: "memory")

#define LDSM4(r0, r1, r2, r3, addr) \
    asm volatile("ldmatrix.sync.aligned.m8n8.x4.shared.b16 {%0,%1,%2,%3}, [%4];" \
                 : "=r"(r0), "=r"(r1), "=r"(r2), "=r"(r3) : "r"(addr))

// FP8 e4m3 MMA with F16 accumulation (fastest measured legacy-path variant)
#define MMA16832H(c, a0, a1, a2, a3, b0, b1) \
    asm volatile( \
        "mma.sync.aligned.m16n8k32.row.col.f16.e4m3.e4m3.f16 " \
        "{%0,%1}, {%2,%3,%4,%5}, {%6,%7}, {%0,%1};" \
        : "+r"((c)[0]), "+r"((c)[1]) \
        : "r"(a0), "r"(a1), "r"(a2), "r"(a3), "r"(b0), "r"(b1))

__device__ __forceinline__ uint8_t f2fp8(float x) {
    return (uint8_t)__nv_cvt_float_to_fp8(x, __NV_SATFINITE, __NV_E4M3);
}

// ---------------- weight folding ----------------
__global__ void fold_w2_kernel(const float* __restrict__ tc_w2,
                               const float* __restrict__ hyp_w) {
    __shared__ float hw[64 * 64];
    __shared__ float row[1024];
    int k = blockIdx.x;
    int tid = threadIdx.x;
    for (int i = tid; i < 4096; i += 256) hw[i] = hyp_w[i];
    for (int i = tid; i < 1024; i += 256) row[i] = tc_w2[(size_t)k * 1024 + i];
    __syncthreads();
#pragma unroll
    for (int t = 0; t < 4; t++) {
        int c = tid + t * 256;
        int j = c >> 6, dp = c & 63;
        float a0 = 0.f, a1 = 0.f;
#pragma unroll 8
        for (int d = 0; d < 64; d += 2) {
            a0 += row[j * 64 + d] * hw[d * 64 + dp];
            a1 += row[j * 64 + d + 1] * hw[(d + 1) * 64 + dp];
        }
        g_w2f[(size_t)k * 1024 + c] = a0 + a1;
    }
}

__global__ void fold_b2_kernel(const float* __restrict__ tc_b2,
                               const float* __restrict__ hyp_w,
                               const float* __restrict__ hyp_b) {
    int c = blockIdx.x * 256 + threadIdx.x;
    if (c < 1024) {
        int j = c >> 6, dp = c & 63;
        float acc = hyp_b[dp];
        for (int d = 0; d < 64; d++) acc += tc_b2[j * 64 + d] * hyp_w[d * 64 + dp];
        g_b2f[c] = acc;
    }
}

// ---------------- fp32 -> fp8 convert (x SCALE_ACT) ----------------
__global__ __launch_bounds__(256) void cvt_fp8_kernel(const float* __restrict__ in,
                                                      uint8_t* __restrict__ out, int n8) {
    int i = blockIdx.x * 256 + threadIdx.x;
    if (i < n8) {
        float4 v0 = ((const float4*)in)[2 * i];
        float4 v1 = ((const float4*)in)[2 * i + 1];
        uint32_t lo = (uint32_t)f2fp8(v0.x * SCALE_ACT) |
                      ((uint32_t)f2fp8(v0.y * SCALE_ACT) << 8) |
                      ((uint32_t)f2fp8(v0.z * SCALE_ACT) << 16) |
                      ((uint32_t)f2fp8(v0.w * SCALE_ACT) << 24);
        uint32_t hi = (uint32_t)f2fp8(v1.x * SCALE_ACT) |
                      ((uint32_t)f2fp8(v1.y * SCALE_ACT) << 8) |
                      ((uint32_t)f2fp8(v1.z * SCALE_ACT) << 16) |
                      ((uint32_t)f2fp8(v1.w * SCALE_ACT) << 24);
        ((uint2*)out)[i] = make_uint2(lo, hi);
    }
}

// ---------------- transpose fp32 -> fp8 (x SCALE_W) ----------------
__global__ void transpose_cvt8_kernel(const float* __restrict__ in,
                                      uint8_t* __restrict__ out, int R, int C) {
    __shared__ float t[32][33];
    int cb = blockIdx.x * 32, rb = blockIdx.y * 32;
    int x = threadIdx.x, y = threadIdx.y;
#pragma unroll
    for (int i = y; i < 32; i += 8) t[i][x] = in[(size_t)(rb + i) * C + cb + x];
    __syncthreads();
#pragma unroll
    for (int i = y; i < 32; i += 8)
        out[(size_t)(cb + i) * R + rb + x] = f2fp8(t[x][i] * SCALE_W);
}

// ---------------- fp8 mma.sync GEMM (f16 acc), 128x256 CTA / 64x64 warp ------
// 2-stage ring (96KB) + 2 CTAs/SM: cross-CTA overlap hides pipeline bubbles.
#define STG 49152
#define NSTG 2

template <int EPI>
__global__ __launch_bounds__(256, 2) void gemm_fp8_kernel(
    const uint8_t* __restrict__ A, const uint8_t* __restrict__ B,
    const float* __restrict__ bias, uint8_t* __restrict__ C8,
    __nv_bfloat16* __restrict__ Cb, int M, int N, int K) {
    extern __shared__ char dsm[];
    __shared__ float sbias[256];

    const int tid = threadIdx.x;
    const int wid = tid >> 5, lane = tid & 31;
    const int wm = wid & 1;        // m half (64 rows)
    const int wn = wid >> 1;       // n quarter (64 cols)
    const int n0 = blockIdx.x * 256;
    const int m0 = blockIdx.y * 128;
    const uint32_t sb = smem_u32(dsm);

    sbias[tid] = bias[n0 + tid];

    const int g = lane >> 3, rin = lane & 7;
    const uint32_t laneA = (uint32_t)((g & 1) * 1024 + (g >> 1) * 128 + rin * 16);
    const uint32_t laneB = (uint32_t)((g >> 1) * 1024 + (g & 1) * 128 + rin * 16);

    uint32_t acc[4][8][2];
#pragma unroll
    for (int i = 0; i < 4; i++)
#pragma unroll
        for (int n = 0; n < 8; n++) {
            acc[i][n][0] = 0u;
            acc[i][n][1] = 0u;
        }

    const int nchunk = K >> 7;   // 128 fp8 per chunk

    auto load_stage = [&](int buf, int kc) {
        const uint32_t sbase = sb + buf * STG;
#pragma unroll
        for (int it = 0; it < 12; it++) {
            int uid = tid + it * 256;
            if (uid < 1024) {
                int rg = uid >> 6, seg = (uid >> 3) & 7, rr = uid & 7;
                cpa16(sbase + uid * 16,
                      A + (size_t)(m0 + rg * 8 + rr) * K + kc * 128 + seg * 16);
            } else {
                int u = uid - 1024;
                int rg = u >> 6, seg = (u >> 3) & 7, rr = u & 7;
                cpa16(sbase + 16384 + u * 16,
                      B + (size_t)(n0 + rg * 8 + rr) * K + kc * 128 + seg * 16);
            }
        }
        CP_COMMIT();
    };

    load_stage(0, 0);
    if (nchunk > 1) load_stage(1, 1);

    for (int kc = 0; kc < nchunk; kc++) {
        if (kc + 1 < nchunk)
            asm volatile("cp.async.wait_group 1;" ::: "memory");
        else
            asm volatile("cp.async.wait_group 0;" ::: "memory");
        __syncthreads();

        const int buf = kc & 1;
        const uint32_t tA = sb + buf * STG + (uint32_t)wm * 8192;
        const uint32_t tB = sb + buf * STG + 16384 + (uint32_t)wn * 8192;

#pragma unroll
        for (int j = 0; j < 4; j++) {          // each j = k32 fp8 (32 bytes)
            uint32_t a[16], b[16];
            const uint32_t jo = (uint32_t)j * 256;
#pragma unroll
            for (int i = 0; i < 4; i++)
                LDSM4(a[4 * i], a[4 * i + 1], a[4 * i + 2], a[4 * i + 3],
                      tA + (uint32_t)i * 2048 + jo + laneA);
#pragma unroll
            for (int p = 0; p < 4; p++)
                LDSM4(b[4 * p], b[4 * p + 1], b[4 * p + 2], b[4 * p + 3],
                      tB + (uint32_t)p * 2048 + jo + laneB);
#pragma unroll
            for (int i = 0; i < 4; i++)
#pragma unroll
                for (int n = 0; n < 8; n++)
                    MMA16832H(acc[i][n], a[4 * i], a[4 * i + 1], a[4 * i + 2], a[4 * i + 3],
                              b[(n >> 1) * 4 + (n & 1) * 2], b[(n >> 1) * 4 + (n & 1) * 2 + 1]);
        }
        __syncthreads();
        if (kc + 2 < nchunk) load_stage(buf, kc + 2);
    }

    // ---------------- epilogue ----------------
    if (EPI == 0) {
        // relu -> fp8 (x SCALE_ACT), staged in SMEM [128][272B]
        uint8_t* sh = (uint8_t*)dsm;
#pragma unroll
        for (int i = 0; i < 4; i++) {
#pragma unroll
            for (int half = 0; half < 2; half++) {
                const int row = 64 * wm + 16 * i + 8 * half + (lane >> 2);
#pragma unroll
                for (int n = 0; n < 8; n++) {
                    const int col = 64 * wn + 8 * n + (lane & 3) * 2;
                    __half2 h2 = *(__half2*)&acc[i][n][half];
                    float v0 = fmaxf(__low2float(h2) * INV_SCALE + sbias[col], 0.f);
                    float v1 = fmaxf(__high2float(h2) * INV_SCALE + sbias[col + 1], 0.f);
                    uint16_t pk = (uint16_t)f2fp8(v0 * SCALE_ACT) |
                                  ((uint16_t)f2fp8(v1 * SCALE_ACT) << 8);
                    *(uint16_t*)(sh + row * 272 + col) = pk;
                }
            }
        }
        __syncthreads();
#pragma unroll
        for (int it = 0; it < 8; it++) {
            int idx = tid + it * 256;          // 2048 uint4 (128 rows x 256B)
            int row = idx >> 4, seg = idx & 15;
            uint4 v = *(const uint4*)(sh + row * 272 + seg * 16);
            *(uint4*)(C8 + (size_t)(m0 + row) * N + n0 + seg * 16) = v;
        }
    } else {
        // fused expmap0, register-only, bf16 output
#pragma unroll
        for (int i = 0; i < 4; i++) {
#pragma unroll
            for (int half = 0; half < 2; half++) {
                const int row = m0 + 64 * wm + 16 * i + 8 * half + (lane >> 2);
                float v[8][2];
                float p = 0.f;
#pragma unroll
                for (int n = 0; n < 8; n++) {
                    const int col = 64 * wn + 8 * n + (lane & 3) * 2;
                    __half2 h2 = *(__half2*)&acc[i][n][half];
                    v[n][0] = __low2float(h2) * INV_SCALE + sbias[col];
                    v[n][1] = __high2float(h2) * INV_SCALE + sbias[col + 1];
                    p += v[n][0] * v[n][0] + v[n][1] * v[n][1];
                }
                p += __shfl_xor_sync(0xffffffffu, p, 1);
                p += __shfl_xor_sync(0xffffffffu, p, 2);
                float nrm = sqrtf(fmaxf(p, EPS_));
                float s = tanhf(nrm) / nrm;
                __nv_bfloat16* dst = Cb + (size_t)row * N + n0 + 64 * wn + (lane & 3) * 2;
#pragma unroll
                for (int n = 0; n < 8; n++) {
                    *(uint32_t*)(dst + 8 * n) =
                        ((uint32_t)__bfloat16_as_ushort(__float2bfloat16(v[n][1] * s)) << 16) |
                        __bfloat16_as_ushort(__float2bfloat16(v[n][0] * s));
                }
            }
        }
    }
}

// ---------------- hyperbolic path search: one CTA per (b, head) -------------
__global__ __launch_bounds__(256, 1) void attn_kernel(const __nv_bfloat16* __restrict__ ek16,
                                                      const float* __restrict__ label,
                                                      const int* __restrict__ y,
                                                      const int* __restrict__ mask_text) {
    extern __shared__ uint32_t skeys[];            // [1024 * 33] bf16x2 words
    __shared__ float2 scf[1024];
    __shared__ int msk[1024];
    __shared__ __align__(16) float q_s[64];
    __shared__ float sq_q_s, fac_s;
    __shared__ float wmx[8], wd_s[8];
    __shared__ float wacc[8][64];

    const int bh = blockIdx.x;
    const int b = bh >> 4;
    const int hh = bh & 15;
    const int tid = threadIdx.x;
    const int w = tid >> 5;
    const int lane = tid & 31;

    const __nv_bfloat16* ekb = ek16 + ((size_t)b * 1024 + hh * 64) * 1024;

#pragma unroll 4
    for (int t = 0; t < 128; t++) {
        const int idx = w * 128 + t;
        uint32_t kw = *(const uint32_t*)(ekb + (size_t)(idx >> 4) * 1024 + (idx & 15) * 64 + lane * 2);
        skeys[idx * 33 + lane] = kw;
    }
    for (int i = tid; i < 1024; i += 256) msk[i] = mask_text[b * 1024 + i];
    if (tid < 64) q_s[tid] = label[(size_t)y[b] * 64 + tid];
    __syncthreads();

#pragma unroll
    for (int i = 0; i < 4; i++) {
        const int idx = tid + i * 256;
        float ps = 0.f;
#pragma unroll
        for (int wd = 0; wd < 32; wd++) {
            uint32_t kw = skeys[idx * 33 + wd];
            __nv_bfloat162 h2 = *(__nv_bfloat162*)&kw;
            float k0 = __bfloat162float(h2.x), k1 = __bfloat162float(h2.y);
            ps += k0 * k0 + k1 * k1;
        }
        float idk = 1.f / fmaxf(1.f - ps, EPS_);
        scf[idx] = make_float2((1.f + ps) * idk, 2.f * idk);
    }
    if (w == 0) {
        float2 qv = *(float2*)(q_s + lane * 2);
        float p = qv.x * qv.x + qv.y * qv.y;
#pragma unroll
        for (int off = 16; off; off >>= 1) p += __shfl_xor_sync(0xffffffffu, p, off);
        if (lane == 0) sq_q_s = p;
    }
    __syncthreads();

    for (int layer = 0; layer < 4; layer++) {
        const float sqq = sq_q_s;
        const float aq = 1.f + sqq;
        const float idq = 1.f / fmaxf(1.f - sqq, EPS_);

        float sc[4], cfv[4], cnv[4];
#pragma unroll
        for (int i = 0; i < 4; i++) {
            const int idx = w * 128 + i * 32 + lane;
            const uint32_t* kp = skeys + idx * 33;
            float dot = 0.f;
#pragma unroll
            for (int wd = 0; wd < 32; wd++) {
                uint32_t kw = kp[wd];
                float2 qv = *(float2*)(q_s + 2 * wd);
                __nv_bfloat162 h2 = *(__nv_bfloat162*)&kw;
                dot += __bfloat162float(h2.x) * qv.x + __bfloat162float(h2.y) * qv.y;
            }
            float2 c = scf[idx];
            cfv[i] = c.x;
            cnv[i] = c.y;
            float x = (aq * c.x - 2.f * dot * c.y) * idq;
            float tt = fmaxf(x - 1.f, 1e-6f);
            float s = -log1pf(tt + sqrtf(tt * (tt + 2.f)));
            sc[i] = msk[idx] ? s : -1e9f;
        }
        float m = fmaxf(fmaxf(sc[0], sc[1]), fmaxf(sc[2], sc[3]));
        float wgt[4];
        float den = 0.f;
#pragma unroll
        for (int i = 0; i < 4; i++) {
            float e = __expf(sc[i] - m);
            den += e * cfv[i];
            wgt[i] = e * cnv[i];
        }

        float acc[64];
#pragma unroll
        for (int wd = 0; wd < 32; wd++) {
            float a0 = 0.f, a1 = 0.f;
#pragma unroll
            for (int i = 0; i < 4; i++) {
                uint32_t kw = skeys[(w * 128 + i * 32 + lane) * 33 + wd];
                __nv_bfloat162 h2 = *(__nv_bfloat162*)&kw;
                a0 += wgt[i] * __bfloat162float(h2.x);
                a1 += wgt[i] * __bfloat162float(h2.y);
            }
            acc[2 * wd] = a0;
            acc[2 * wd + 1] = a1;
        }

        float mw = m;
#pragma unroll
        for (int off = 16; off; off >>= 1) mw = fmaxf(mw, __shfl_xor_sync(0xffffffffu, mw, off));
        float s = __expf(m - mw);
        den *= s;
#pragma unroll
        for (int d = 0; d < 64; d++) acc[d] *= s;
#pragma unroll
        for (int off = 16; off; off >>= 1) {
            den += __shfl_xor_sync(0xffffffffu, den, off);
#pragma unroll
            for (int d = 0; d < 64; d++) acc[d] += __shfl_xor_sync(0xffffffffu, acc[d], off);
        }
        if (lane == 0) {
            wmx[w] = mw;
            wd_s[w] = den;
#pragma unroll
            for (int d = 0; d < 64; d++) wacc[w][d] = acc[d];
        }
        __syncthreads();

        if (tid < 64) {
            float M = wmx[0];
#pragma unroll
            for (int ww = 1; ww < 8; ww++) M = fmaxf(M, wmx[ww]);
            float num = 0.f, D = 0.f;
#pragma unroll
            for (int ww = 0; ww < 8; ww++) {
                float al = __expf(wmx[ww] - M);
                num += al * wacc[ww][tid];
                D += al * wd_s[ww];
            }
            q_s[tid] = num / D;
        }
        __syncthreads();
        if (w == 0) {
            float2 mv = *(float2*)(q_s + lane * 2);
            float p = mv.x * mv.x + mv.y * mv.y;
#pragma unroll
            for (int off = 16; off; off >>= 1) p += __shfl_xor_sync(0xffffffffu, p, off);
            if (lane == 0) {
                float r = 1.f / (1.f + sqrtf(fmaxf(1.f - p, EPS_)));
                fac_s = r;
                sq_q_s = p * r * r;
            }
        }
        __syncthreads();
        if (tid < 64) q_s[tid] *= fac_s;
        __syncthreads();
    }
    if (tid < 64) g_qv[(size_t)bh * 64 + tid] = q_s[tid];
    if (tid == 0) g_sqq[bh] = sq_q_s;
}

// ---------------- label distances + aggregator MLP --------------------------
__global__ __launch_bounds__(128) void label_mlp_kernel(
    const float* __restrict__ label,
    const float* __restrict__ w1, const float* __restrict__ b1,
    const float* __restrict__ w2, const float* __restrict__ b2,
    const float* __restrict__ w3, const float* __restrict__ b3,
    const float* __restrict__ w4, const float* __restrict__ b4,
    const int* __restrict__ mask_label, float* __restrict__ out) {
    __shared__ float lab[128][65];
    __shared__ float qs[16 * 64];
    __shared__ float P[16], Qc[16];
    __shared__ float sw1[512], sb1[32], sw2[1024], sb2[32], sw3[512], sb3[16], sw4[16], sb4s[1];

    const int b = blockIdx.y;
    const int base = blockIdx.x * 128;
    const int tid = threadIdx.x;

    for (int i = tid; i < 128 * 64; i += 128) lab[i >> 6][i & 63] = label[(size_t)base * 64 + i];
    for (int i = tid; i < 1024; i += 128) qs[i] = g_qv[(size_t)b * 1024 + i];
    if (tid < 16) {
        float s = g_sqq[b * 16 + tid];
        float inv = 1.f / fmaxf(1.f - s, EPS_);
        P[tid] = (1.f + s) * inv;
        Qc[tid] = 4.f * inv;
    }
    for (int i = tid; i < 512; i += 128) sw1[i] = w1[i];
    for (int i = tid; i < 1024; i += 128) sw2[i] = w2[i];
    for (int i = tid; i < 512; i += 128) sw3[i] = w3[i];
    if (tid < 32) { sb1[tid] = b1[tid]; sb2[tid] = b2[tid]; }
    if (tid < 16) { sb3[tid] = b3[tid]; sw4[tid] = w4[tid]; }
    if (tid == 0) sb4s[0] = b4[0];
    __syncthreads();

    float sq_l = 0.f;
#pragma unroll 8
    for (int d = 0; d < 64; d++) { float v = lab[tid][d]; sq_l += v * v; }
    const float invl = 1.f / fmaxf(1.f - sq_l, EPS_);
    const float L1 = (1.f + sq_l) * invl;

    float dh[16];
#pragma unroll
    for (int h = 0; h < 16; h++) {
        float dot = 0.f;
#pragma unroll 8
        for (int d = 0; d < 64; d++) dot += qs[h * 64 + d] * lab[tid][d];
        float x = P[h] * L1 - Qc[h] * invl * dot;
        float tt = fmaxf(x - 1.f, 1e-6f);
        dh[h] = log1pf(tt + sqrtf(tt * (tt + 2.f)));
    }
    float x1[32];
#pragma unroll
    for (int j = 0; j < 32; j++) {
        float a = sb1[j];
#pragma unroll
        for (int h = 0; h < 16; h++) a += dh[h] * sw1[h * 32 + j];
        x1[j] = fmaxf(a, 0.f);
    }
    float x2[32];
#pragma unroll
    for (int j = 0; j < 32; j++) {
        float a = sb2[j];
#pragma unroll
        for (int i = 0; i < 32; i++) a += x1[i] * sw2[i * 32 + j];
        x2[j] = fmaxf(a, 0.f);
    }
    float x3[16];
#pragma unroll
    for (int j = 0; j < 16; j++) {
        float a = sb3[j];
#pragma unroll
        for (int i = 0; i < 32; i++) a += x2[i] * sw3[i * 16 + j];
        x3[j] = fmaxf(a, 0.f);
    }
    float val = sb4s[0];
#pragma unroll
    for (int h = 0; h < 16; h++) val += x3[h] * sw4[h];

    const int n = base + tid;
    out[(size_t)b * NLABEL + n] = (mask_label[(size_t)b * NLABEL + n] > 0) ? val : -500.f;
}

// ---------------- launch -----------------------------------------------------
extern "C" void kernel_launch(void* const* d_in, const int* in_sizes, int n_in,
                              void* d_out, int out_size) {
    const float* e = (const float*)d_in[0];
    const float* label = (const float*)d_in[1];
    const float* tc_w1 = (const float*)d_in[2];
    const float* tc_b1 = (const float*)d_in[3];
    const float* tc_w2 = (const float*)d_in[4];
    const float* tc_b2 = (const float*)d_in[5];
    const float* hyp_w = (const float*)d_in[6];
    const float* hyp_b = (const float*)d_in[7];
    const float* aw1 = (const float*)d_in[8];
    const float* ab1 = (const float*)d_in[9];
    const float* aw2 = (const float*)d_in[10];
    const float* ab2 = (const float*)d_in[11];
    const float* aw3 = (const float*)d_in[12];
    const float* ab3 = (const float*)d_in[13];
    const float* aw4 = (const float*)d_in[14];
    const float* ab4 = (const float*)d_in[15];
    const int* y = (const int*)d_in[16];
    const int* mt = (const int*)d_in[17];
    const int* ml = (const int*)d_in[18];
    float* out = (float*)d_out;

    uint8_t *e8, *h18, *w1t8, *w2t8;
    __nv_bfloat16* ek16;
    float *w2fp, *b2fp;
    cudaGetSymbolAddress((void**)&e8, g_e8);
    cudaGetSymbolAddress((void**)&h18, g_h18);
    cudaGetSymbolAddress((void**)&w1t8, g_w1t8);
    cudaGetSymbolAddress((void**)&w2t8, g_w2t8);
    cudaGetSymbolAddress((void**)&ek16, g_ek16);
    cudaGetSymbolAddress((void**)&w2fp, g_w2f);
    cudaGetSymbolAddress((void**)&b2fp, g_b2f);

    const int smem_bytes = NSTG * STG;   // 96KB -> 2 CTAs/SM
    cudaFuncSetAttribute(gemm_fp8_kernel<0>, cudaFuncAttributeMaxDynamicSharedMemorySize,
                         smem_bytes);
    cudaFuncSetAttribute(gemm_fp8_kernel<1>, cudaFuncAttributeMaxDynamicSharedMemorySize,
                         smem_bytes);
    const int attn_smem = 1024 * 33 * 4;  // 132KB
    cudaFuncSetAttribute(attn_kernel, cudaFuncAttributeMaxDynamicSharedMemorySize, attn_smem);

    // launch order: gemm1 in profiler slot #4
    cvt_fp8_kernel<<<(MROWS * 1024 / 8 + 255) / 256, 256>>>(e, e8, MROWS * 1024 / 8);
    transpose_cvt8_kernel<<<dim3(2048 / 32, 1024 / 32), dim3(32, 8)>>>(tc_w1, w1t8, 1024, 2048);
    fold_w2_kernel<<<2048, 256>>>(tc_w2, hyp_w);

    // GEMM1 (launch #4): h1 = relu(e @ w1 + b1) -> fp8
    gemm_fp8_kernel<0><<<dim3(8, 256), 256, smem_bytes>>>(
        e8, w1t8, tc_b1, h18, nullptr, MROWS, 2048, 1024);

    fold_b2_kernel<<<4, 256>>>(tc_b2, hyp_w, hyp_b);
    transpose_cvt8_kernel<<<dim3(1024 / 32, 2048 / 32), dim3(32, 8)>>>(w2fp, w2t8, 2048, 1024);

    // GEMM2: ek = expmap0(h1 @ w2f + b2f) -> bf16
    gemm_fp8_kernel<1><<<dim3(4, 256), 256, smem_bytes>>>(
        h18, w2t8, b2fp, nullptr, ek16, MROWS, 1024, 2048);

    attn_kernel<<<512, 256, attn_smem>>>(ek16, label, y, mt);
    label_mlp_kernel<<<dim3(NLABEL / 128, BBATCH), 128>>>(label, aw1, ab1, aw2, ab2,
                                                          aw3, ab3, aw4, ab4, ml, out);
}

// round 12
// speedup vs baseline: 1.9699x; 1.0116x over previous
#include <cuda_runtime.h>
#include <cuda_bf16.h>
#include <cuda_fp8.h>
#include <cuda_fp16.h>
#include <math.h>
#include <stdint.h>

// Problem constants
#define BBATCH 32
#define NLABEL 8192
#define MROWS 32768
#define EPS_ 1e-12f

#define SCALE_ACT 16.f
#define SCALE_W 64.f
#define INV_SCALE (1.f / 1024.f)

// ---------------- device scratch ----------------
__device__ uint8_t g_e8[(size_t)MROWS * 1024];
__device__ uint8_t g_h18[(size_t)MROWS * 2048];
__device__ __nv_bfloat16 g_ek16[(size_t)MROWS * 1024];
__device__ float g_w2f[2048 * 1024];
__device__ float g_b2f[1024];
__device__ uint8_t g_w1t8[2048 * 1024];
__device__ uint8_t g_w2t8[1024 * 2048];
__device__ float g_qv[512 * 64];
__device__ float g_sqq[512];

// ---------------- PTX helpers ----------------
__device__ __forceinline__ uint32_t smem_u32(const void* p) {
    uint32_t a;
    asm("{ .reg .u64 t; cvta.to.shared.u64 t, %1; cvt.u32.u64 %0, t; }" : "=r"(a) : "l"(p));
    return a;
}
__device__ __forceinline__ void cpa16(uint32_t saddr, const void* g) {
    asm volatile("cp.async.cg.shared.global [%0], [%1], 16;" :: "r"(saddr), "l"(g));
}
#define CP_COMMIT() asm volatile("cp.async.commit_group;" ::: "memory")

#define LDSM4(r0, r1, r2, r3, addr) \
    asm volatile("ldmatrix.sync.aligned.m8n8.x4.shared.b16 {%0,%1,%2,%3}, [%4];" \
                 : "=r"(r0), "=r"(r1), "=r"(r2), "=r"(r3) : "r"(addr))

// FP8 e4m3 MMA with F16 accumulation (fastest measured legacy-path variant)
#define MMA16832H(c, a0, a1, a2, a3, b0, b1) \
    asm volatile( \
        "mma.sync.aligned.m16n8k32.row.col.f16.e4m3.e4m3.f16 " \
        "{%0,%1}, {%2,%3,%4,%5}, {%6,%7}, {%0,%1};" \
        : "+r"((c)[0]), "+r"((c)[1]) \
        : "r"(a0), "r"(a1), "r"(a2), "r"(a3), "r"(b0), "r"(b1))

__device__ __forceinline__ uint8_t f2fp8(float x) {
    return (uint8_t)__nv_cvt_float_to_fp8(x, __NV_SATFINITE, __NV_E4M3);
}

// ---------------- weight folding ----------------
__global__ void fold_w2_kernel(const float* __restrict__ tc_w2,
                               const float* __restrict__ hyp_w) {
    __shared__ float hw[64 * 64];
    __shared__ float row[1024];
    int k = blockIdx.x;
    int tid = threadIdx.x;
    for (int i = tid; i < 4096; i += 256) hw[i] = hyp_w[i];
    for (int i = tid; i < 1024; i += 256) row[i] = tc_w2[(size_t)k * 1024 + i];
    __syncthreads();
#pragma unroll
    for (int t = 0; t < 4; t++) {
        int c = tid + t * 256;
        int j = c >> 6, dp = c & 63;
        float a0 = 0.f, a1 = 0.f;
#pragma unroll 8
        for (int d = 0; d < 64; d += 2) {
            a0 += row[j * 64 + d] * hw[d * 64 + dp];
            a1 += row[j * 64 + d + 1] * hw[(d + 1) * 64 + dp];
        }
        g_w2f[(size_t)k * 1024 + c] = a0 + a1;
    }
}

__global__ void fold_b2_kernel(const float* __restrict__ tc_b2,
                               const float* __restrict__ hyp_w,
                               const float* __restrict__ hyp_b) {
    int c = blockIdx.x * 256 + threadIdx.x;
    if (c < 1024) {
        int j = c >> 6, dp = c & 63;
        float acc = hyp_b[dp];
        for (int d = 0; d < 64; d++) acc += tc_b2[j * 64 + d] * hyp_w[d * 64 + dp];
        g_b2f[c] = acc;
    }
}

// ---------------- fp32 -> fp8 convert (x SCALE_ACT), 16 floats/thread --------
__global__ __launch_bounds__(256) void cvt_fp8_kernel(const float* __restrict__ in,
                                                      uint8_t* __restrict__ out, int n16) {
    int i = blockIdx.x * 256 + threadIdx.x;
    if (i < n16) {
        uint32_t w[4];
#pragma unroll
        for (int q = 0; q < 4; q++) {
            float4 v = ((const float4*)in)[4 * i + q];
            w[q] = (uint32_t)f2fp8(v.x * SCALE_ACT) |
                   ((uint32_t)f2fp8(v.y * SCALE_ACT) << 8) |
                   ((uint32_t)f2fp8(v.z * SCALE_ACT) << 16) |
                   ((uint32_t)f2fp8(v.w * SCALE_ACT) << 24);
        }
        ((uint4*)out)[i] = make_uint4(w[0], w[1], w[2], w[3]);
    }
}

// ---------------- transpose fp32 -> fp8 (x SCALE_W) ----------------
__global__ void transpose_cvt8_kernel(const float* __restrict__ in,
                                      uint8_t* __restrict__ out, int R, int C) {
    __shared__ float t[32][33];
    int cb = blockIdx.x * 32, rb = blockIdx.y * 32;
    int x = threadIdx.x, y = threadIdx.y;
#pragma unroll
    for (int i = y; i < 32; i += 8) t[i][x] = in[(size_t)(rb + i) * C + cb + x];
    __syncthreads();
#pragma unroll
    for (int i = y; i < 32; i += 8)
        out[(size_t)(cb + i) * R + rb + x] = f2fp8(t[x][i] * SCALE_W);
}

// ---------------- fp8 mma.sync GEMM (f16 acc), 128x256 CTA / 64x64 warp ------
// 2-stage ring (96KB) + 2 CTAs/SM (best measured config, R11)
#define STG 49152
#define NSTG 2

template <int EPI>
__global__ __launch_bounds__(256, 2) void gemm_fp8_kernel(
    const uint8_t* __restrict__ A, const uint8_t* __restrict__ B,
    const float* __restrict__ bias, uint8_t* __restrict__ C8,
    __nv_bfloat16* __restrict__ Cb, int M, int N, int K) {
    extern __shared__ char dsm[];
    __shared__ float sbias[256];

    const int tid = threadIdx.x;
    const int wid = tid >> 5, lane = tid & 31;
    const int wm = wid & 1;        // m half (64 rows)
    const int wn = wid >> 1;       // n quarter (64 cols)
    const int n0 = blockIdx.x * 256;
    const int m0 = blockIdx.y * 128;
    const uint32_t sb = smem_u32(dsm);

    sbias[tid] = bias[n0 + tid];

    const int g = lane >> 3, rin = lane & 7;
    const uint32_t laneA = (uint32_t)((g & 1) * 1024 + (g >> 1) * 128 + rin * 16);
    const uint32_t laneB = (uint32_t)((g >> 1) * 1024 + (g & 1) * 128 + rin * 16);

    uint32_t acc[4][8][2];
#pragma unroll
    for (int i = 0; i < 4; i++)
#pragma unroll
        for (int n = 0; n < 8; n++) {
            acc[i][n][0] = 0u;
            acc[i][n][1] = 0u;
        }

    const int nchunk = K >> 7;   // 128 fp8 per chunk

    auto load_stage = [&](int buf, int kc) {
        const uint32_t sbase = sb + buf * STG;
#pragma unroll
        for (int it = 0; it < 12; it++) {
            int uid = tid + it * 256;
            if (uid < 1024) {
                int rg = uid >> 6, seg = (uid >> 3) & 7, rr = uid & 7;
                cpa16(sbase + uid * 16,
                      A + (size_t)(m0 + rg * 8 + rr) * K + kc * 128 + seg * 16);
            } else {
                int u = uid - 1024;
                int rg = u >> 6, seg = (u >> 3) & 7, rr = u & 7;
                cpa16(sbase + 16384 + u * 16,
                      B + (size_t)(n0 + rg * 8 + rr) * K + kc * 128 + seg * 16);
            }
        }
        CP_COMMIT();
    };

    load_stage(0, 0);
    if (nchunk > 1) load_stage(1, 1);

    for (int kc = 0; kc < nchunk; kc++) {
        if (kc + 1 < nchunk)
            asm volatile("cp.async.wait_group 1;" ::: "memory");
        else
            asm volatile("cp.async.wait_group 0;" ::: "memory");
        __syncthreads();

        const int buf = kc & 1;
        const uint32_t tA = sb + buf * STG + (uint32_t)wm * 8192;
        const uint32_t tB = sb + buf * STG + 16384 + (uint32_t)wn * 8192;

#pragma unroll
        for (int j = 0; j < 4; j++) {          // each j = k32 fp8 (32 bytes)
            uint32_t a[16], b[16];
            const uint32_t jo = (uint32_t)j * 256;
#pragma unroll
            for (int i = 0; i < 4; i++)
                LDSM4(a[4 * i], a[4 * i + 1], a[4 * i + 2], a[4 * i + 3],
                      tA + (uint32_t)i * 2048 + jo + laneA);
#pragma unroll
            for (int p = 0; p < 4; p++)
                LDSM4(b[4 * p], b[4 * p + 1], b[4 * p + 2], b[4 * p + 3],
                      tB + (uint32_t)p * 2048 + jo + laneB);
#pragma unroll
            for (int i = 0; i < 4; i++)
#pragma unroll
                for (int n = 0; n < 8; n++)
                    MMA16832H(acc[i][n], a[4 * i], a[4 * i + 1], a[4 * i + 2], a[4 * i + 3],
                              b[(n >> 1) * 4 + (n & 1) * 2], b[(n >> 1) * 4 + (n & 1) * 2 + 1]);
        }
        __syncthreads();
        if (kc + 2 < nchunk) load_stage(buf, kc + 2);
    }

    // ---------------- epilogue ----------------
    if (EPI == 0) {
        // relu -> fp8 (x SCALE_ACT), staged in SMEM [128][272B]
        uint8_t* sh = (uint8_t*)dsm;
#pragma unroll
        for (int i = 0; i < 4; i++) {
#pragma unroll
            for (int half = 0; half < 2; half++) {
                const int row = 64 * wm + 16 * i + 8 * half + (lane >> 2);
#pragma unroll
                for (int n = 0; n < 8; n++) {
                    const int col = 64 * wn + 8 * n + (lane & 3) * 2;
                    __half2 h2 = *(__half2*)&acc[i][n][half];
                    float v0 = fmaxf(__low2float(h2) * INV_SCALE + sbias[col], 0.f);
                    float v1 = fmaxf(__high2float(h2) * INV_SCALE + sbias[col + 1], 0.f);
                    uint16_t pk = (uint16_t)f2fp8(v0 * SCALE_ACT) |
                                  ((uint16_t)f2fp8(v1 * SCALE_ACT) << 8);
                    *(uint16_t*)(sh + row * 272 + col) = pk;
                }
            }
        }
        __syncthreads();
#pragma unroll
        for (int it = 0; it < 8; it++) {
            int idx = tid + it * 256;          // 2048 uint4 (128 rows x 256B)
            int row = idx >> 4, seg = idx & 15;
            uint4 v = *(const uint4*)(sh + row * 272 + seg * 16);
            *(uint4*)(C8 + (size_t)(m0 + row) * N + n0 + seg * 16) = v;
        }
    } else {
        // fused expmap0, register-only, bf16 output
#pragma unroll
        for (int i = 0; i < 4; i++) {
#pragma unroll
            for (int half = 0; half < 2; half++) {
                const int row = m0 + 64 * wm + 16 * i + 8 * half + (lane >> 2);
                float v[8][2];
                float p = 0.f;
#pragma unroll
                for (int n = 0; n < 8; n++) {
                    const int col = 64 * wn + 8 * n + (lane & 3) * 2;
                    __half2 h2 = *(__half2*)&acc[i][n][half];
                    v[n][0] = __low2float(h2) * INV_SCALE + sbias[col];
                    v[n][1] = __high2float(h2) * INV_SCALE + sbias[col + 1];
                    p += v[n][0] * v[n][0] + v[n][1] * v[n][1];
                }
                p += __shfl_xor_sync(0xffffffffu, p, 1);
                p += __shfl_xor_sync(0xffffffffu, p, 2);
                float nrm = sqrtf(fmaxf(p, EPS_));
                float s = tanhf(nrm) / nrm;
                __nv_bfloat16* dst = Cb + (size_t)row * N + n0 + 64 * wn + (lane & 3) * 2;
#pragma unroll
                for (int n = 0; n < 8; n++) {
                    *(uint32_t*)(dst + 8 * n) =
                        ((uint32_t)__bfloat16_as_ushort(__float2bfloat16(v[n][1] * s)) << 16) |
                        __bfloat16_as_ushort(__float2bfloat16(v[n][0] * s));
                }
            }
        }
    }
}

// ---------------- hyperbolic path search: one CTA per (b, head) -------------
// Phase 1: lane owns 4 keys (scores); scalar warp reductions only.
// Phase 2: weights parked in SMEM; lane owns one dim-pair over the warp's
//          128 keys -> zero vector shuffles.
__global__ __launch_bounds__(256, 1) void attn_kernel(const __nv_bfloat16* __restrict__ ek16,
                                                      const float* __restrict__ label,
                                                      const int* __restrict__ y,
                                                      const int* __restrict__ mask_text) {
    extern __shared__ uint32_t skeys[];            // [1024 * 33] bf16x2 words
    __shared__ float2 scf[1024];
    __shared__ float wgt_s[1024];
    __shared__ int msk[1024];
    __shared__ __align__(16) float q_s[64];
    __shared__ float sq_q_s, fac_s;
    __shared__ float wmx[8], wd_s[8];
    __shared__ float wacc[8][64];

    const int bh = blockIdx.x;
    const int b = bh >> 4;
    const int hh = bh & 15;
    const int tid = threadIdx.x;
    const int w = tid >> 5;
    const int lane = tid & 31;

    const __nv_bfloat16* ekb = ek16 + ((size_t)b * 1024 + hh * 64) * 1024;

#pragma unroll 4
    for (int t = 0; t < 128; t++) {
        const int idx = w * 128 + t;
        uint32_t kw = *(const uint32_t*)(ekb + (size_t)(idx >> 4) * 1024 + (idx & 15) * 64 + lane * 2);
        skeys[idx * 33 + lane] = kw;
    }
    for (int i = tid; i < 1024; i += 256) msk[i] = mask_text[b * 1024 + i];
    if (tid < 64) q_s[tid] = label[(size_t)y[b] * 64 + tid];
    __syncthreads();

    // per-key invariant factors (thread-local)
#pragma unroll
    for (int i = 0; i < 4; i++) {
        const int idx = tid + i * 256;
        float ps = 0.f;
#pragma unroll
        for (int wd = 0; wd < 32; wd++) {
            uint32_t kw = skeys[idx * 33 + wd];
            __nv_bfloat162 h2 = *(__nv_bfloat162*)&kw;
            float k0 = __bfloat162float(h2.x), k1 = __bfloat162float(h2.y);
            ps += k0 * k0 + k1 * k1;
        }
        float idk = 1.f / fmaxf(1.f - ps, EPS_);
        scf[idx] = make_float2((1.f + ps) * idk, 2.f * idk);
    }
    if (w == 0) {
        float2 qv = *(float2*)(q_s + lane * 2);
        float p = qv.x * qv.x + qv.y * qv.y;
#pragma unroll
        for (int off = 16; off; off >>= 1) p += __shfl_xor_sync(0xffffffffu, p, off);
        if (lane == 0) sq_q_s = p;
    }
    __syncthreads();

    for (int layer = 0; layer < 4; layer++) {
        const float sqq = sq_q_s;
        const float aq = 1.f + sqq;
        const float idq = 1.f / fmaxf(1.f - sqq, EPS_);

        // ---- phase 1: scores for this lane's 4 keys ----
        float sc[4], cfv[4], cnv[4];
#pragma unroll
        for (int i = 0; i < 4; i++) {
            const int idx = w * 128 + i * 32 + lane;
            const uint32_t* kp = skeys + idx * 33;
            float dot = 0.f;
#pragma unroll
            for (int wd = 0; wd < 32; wd++) {
                uint32_t kw = kp[wd];
                float2 qv = *(float2*)(q_s + 2 * wd);
                __nv_bfloat162 h2 = *(__nv_bfloat162*)&kw;
                dot += __bfloat162float(h2.x) * qv.x + __bfloat162float(h2.y) * qv.y;
            }
            float2 c = scf[idx];
            cfv[i] = c.x;
            cnv[i] = c.y;
            float x = (aq * c.x - 2.f * dot * c.y) * idq;
            float tt = fmaxf(x - 1.f, 1e-6f);
            float s = -log1pf(tt + sqrtf(tt * (tt + 2.f)));
            sc[i] = msk[idx] ? s : -1e9f;
        }
        // scalar warp reductions: max then denominator
        float mw = fmaxf(fmaxf(sc[0], sc[1]), fmaxf(sc[2], sc[3]));
#pragma unroll
        for (int off = 16; off; off >>= 1) mw = fmaxf(mw, __shfl_xor_sync(0xffffffffu, mw, off));
        float den = 0.f;
#pragma unroll
        for (int i = 0; i < 4; i++) {
            float e = __expf(sc[i] - mw);
            den += e * cfv[i];
            wgt_s[w * 128 + i * 32 + lane] = e * cnv[i];
        }
#pragma unroll
        for (int off = 16; off; off >>= 1) den += __shfl_xor_sync(0xffffffffu, den, off);
        if (lane == 0) { wmx[w] = mw; wd_s[w] = den; }
        __syncwarp();

        // ---- phase 2: lane owns one dim-pair across the warp's 128 keys ----
        float a0 = 0.f, a1 = 0.f;
#pragma unroll 8
        for (int t = 0; t < 128; t++) {
            const int idx = w * 128 + t;
            float wg = wgt_s[idx];
            uint32_t kw = skeys[idx * 33 + lane];
            __nv_bfloat162 h2 = *(__nv_bfloat162*)&kw;
            a0 += wg * __bfloat162float(h2.x);
            a1 += wg * __bfloat162float(h2.y);
        }
        wacc[w][2 * lane] = a0;
        wacc[w][2 * lane + 1] = a1;
        __syncthreads();

        if (tid < 64) {
            float M = wmx[0];
#pragma unroll
            for (int ww = 1; ww < 8; ww++) M = fmaxf(M, wmx[ww]);
            float num = 0.f, D = 0.f;
#pragma unroll
            for (int ww = 0; ww < 8; ww++) {
                float al = __expf(wmx[ww] - M);
                num += al * wacc[ww][tid];
                D += al * wd_s[ww];
            }
            q_s[tid] = num / D;        // Einstein midpoint (Klein)
        }
        __syncthreads();
        if (w == 0) {
            float2 mv = *(float2*)(q_s + lane * 2);
            float p = mv.x * mv.x + mv.y * mv.y;
#pragma unroll
            for (int off = 16; off; off >>= 1) p += __shfl_xor_sync(0xffffffffu, p, off);
            if (lane == 0) {
                float r = 1.f / (1.f + sqrtf(fmaxf(1.f - p, EPS_)));   // k2p
                fac_s = r;
                sq_q_s = p * r * r;
            }
        }
        __syncthreads();
        if (tid < 64) q_s[tid] *= fac_s;
        __syncthreads();
    }
    if (tid < 64) g_qv[(size_t)bh * 64 + tid] = q_s[tid];
    if (tid == 0) g_sqq[bh] = sq_q_s;
}

// ---------------- label distances + aggregator MLP --------------------------
__global__ __launch_bounds__(128) void label_mlp_kernel(
    const float* __restrict__ label,
    const float* __restrict__ w1, const float* __restrict__ b1,
    const float* __restrict__ w2, const float* __restrict__ b2,
    const float* __restrict__ w3, const float* __restrict__ b3,
    const float* __restrict__ w4, const float* __restrict__ b4,
    const int* __restrict__ mask_label, float* __restrict__ out) {
    __shared__ float lab[128][65];
    __shared__ float qs[16 * 64];
    __shared__ float P[16], Qc[16];
    __shared__ float sw1[512], sb1[32], sw2[1024], sb2[32], sw3[512], sb3[16], sw4[16], sb4s[1];

    const int b = blockIdx.y;
    const int base = blockIdx.x * 128;
    const int tid = threadIdx.x;

    for (int i = tid; i < 128 * 64; i += 128) lab[i >> 6][i & 63] = label[(size_t)base * 64 + i];
    for (int i = tid; i < 1024; i += 128) qs[i] = g_qv[(size_t)b * 1024 + i];
    if (tid < 16) {
        float s = g_sqq[b * 16 + tid];
        float inv = 1.f / fmaxf(1.f - s, EPS_);
        P[tid] = (1.f + s) * inv;
        Qc[tid] = 4.f * inv;
    }
    for (int i = tid; i < 512; i += 128) sw1[i] = w1[i];
    for (int i = tid; i < 1024; i += 128) sw2[i] = w2[i];
    for (int i = tid; i < 512; i += 128) sw3[i] = w3[i];
    if (tid < 32) { sb1[tid] = b1[tid]; sb2[tid] = b2[tid]; }
    if (tid < 16) { sb3[tid] = b3[tid]; sw4[tid] = w4[tid]; }
    if (tid == 0) sb4s[0] = b4[0];
    __syncthreads();

    float sq_l = 0.f;
#pragma unroll 8
    for (int d = 0; d < 64; d++) { float v = lab[tid][d]; sq_l += v * v; }
    const float invl = 1.f / fmaxf(1.f - sq_l, EPS_);
    const float L1 = (1.f + sq_l) * invl;

    float dh[16];
#pragma unroll
    for (int h = 0; h < 16; h++) {
        float dot = 0.f;
#pragma unroll 8
        for (int d = 0; d < 64; d++) dot += qs[h * 64 + d] * lab[tid][d];
        float x = P[h] * L1 - Qc[h] * invl * dot;
        float tt = fmaxf(x - 1.f, 1e-6f);
        dh[h] = log1pf(tt + sqrtf(tt * (tt + 2.f)));
    }
    float x1[32];
#pragma unroll
    for (int j = 0; j < 32; j++) {
        float a = sb1[j];
#pragma unroll
        for (int h = 0; h < 16; h++) a += dh[h] * sw1[h * 32 + j];
        x1[j] = fmaxf(a, 0.f);
    }
    float x2[32];
#pragma unroll
    for (int j = 0; j < 32; j++) {
        float a = sb2[j];
#pragma unroll
        for (int i = 0; i < 32; i++) a += x1[i] * sw2[i * 32 + j];
        x2[j] = fmaxf(a, 0.f);
    }
    float x3[16];
#pragma unroll
    for (int j = 0; j < 16; j++) {
        float a = sb3[j];
#pragma unroll
        for (int i = 0; i < 32; i++) a += x2[i] * sw3[i * 16 + j];
        x3[j] = fmaxf(a, 0.f);
    }
    float val = sb4s[0];
#pragma unroll
    for (int h = 0; h < 16; h++) val += x3[h] * sw4[h];

    const int n = base + tid;
    out[(size_t)b * NLABEL + n] = (mask_label[(size_t)b * NLABEL + n] > 0) ? val : -500.f;
}

// ---------------- launch -----------------------------------------------------
extern "C" void kernel_launch(void* const* d_in, const int* in_sizes, int n_in,
                              void* d_out, int out_size) {
    const float* e = (const float*)d_in[0];
    const float* label = (const float*)d_in[1];
    const float* tc_w1 = (const float*)d_in[2];
    const float* tc_b1 = (const float*)d_in[3];
    const float* tc_w2 = (const float*)d_in[4];
    const float* tc_b2 = (const float*)d_in[5];
    const float* hyp_w = (const float*)d_in[6];
    const float* hyp_b = (const float*)d_in[7];
    const float* aw1 = (const float*)d_in[8];
    const float* ab1 = (const float*)d_in[9];
    const float* aw2 = (const float*)d_in[10];
    const float* ab2 = (const float*)d_in[11];
    const float* aw3 = (const float*)d_in[12];
    const float* ab3 = (const float*)d_in[13];
    const float* aw4 = (const float*)d_in[14];
    const float* ab4 = (const float*)d_in[15];
    const int* y = (const int*)d_in[16];
    const int* mt = (const int*)d_in[17];
    const int* ml = (const int*)d_in[18];
    float* out = (float*)d_out;

    uint8_t *e8, *h18, *w1t8, *w2t8;
    __nv_bfloat16* ek16;
    float *w2fp, *b2fp;
    cudaGetSymbolAddress((void**)&e8, g_e8);
    cudaGetSymbolAddress((void**)&h18, g_h18);
    cudaGetSymbolAddress((void**)&w1t8, g_w1t8);
    cudaGetSymbolAddress((void**)&w2t8, g_w2t8);
    cudaGetSymbolAddress((void**)&ek16, g_ek16);
    cudaGetSymbolAddress((void**)&w2fp, g_w2f);
    cudaGetSymbolAddress((void**)&b2fp, g_b2f);

    const int smem_bytes = NSTG * STG;   // 96KB -> 2 CTAs/SM
    cudaFuncSetAttribute(gemm_fp8_kernel<0>, cudaFuncAttributeMaxDynamicSharedMemorySize,
                         smem_bytes);
    cudaFuncSetAttribute(gemm_fp8_kernel<1>, cudaFuncAttributeMaxDynamicSharedMemorySize,
                         smem_bytes);
    const int attn_smem = 1024 * 33 * 4;  // 132KB
    cudaFuncSetAttribute(attn_kernel, cudaFuncAttributeMaxDynamicSharedMemorySize, attn_smem);

    // launch order: gemm1 in profiler slot #4
    cvt_fp8_kernel<<<(MROWS * 1024 / 16 + 255) / 256, 256>>>(e, e8, MROWS * 1024 / 16);
    transpose_cvt8_kernel<<<dim3(2048 / 32, 1024 / 32), dim3(32, 8)>>>(tc_w1, w1t8, 1024, 2048);
    fold_w2_kernel<<<2048, 256>>>(tc_w2, hyp_w);

    // GEMM1 (launch #4): h1 = relu(e @ w1 + b1) -> fp8
    gemm_fp8_kernel<0><<<dim3(8, 256), 256, smem_bytes>>>(
        e8, w1t8, tc_b1, h18, nullptr, MROWS, 2048, 1024);

    fold_b2_kernel<<<4, 256>>>(tc_b2, hyp_w, hyp_b);
    transpose_cvt8_kernel<<<dim3(1024 / 32, 2048 / 32), dim3(32, 8)>>>(w2fp, w2t8, 2048, 1024);

    // GEMM2: ek = expmap0(h1 @ w2f + b2f) -> bf16
    gemm_fp8_kernel<1><<<dim3(4, 256), 256, smem_bytes>>>(
        h18, w2t8, b2fp, nullptr, ek16, MROWS, 1024, 2048);

    attn_kernel<<<512, 256, attn_smem>>>(ek16, label, y, mt);
    label_mlp_kernel<<<dim3(NLABEL / 128, BBATCH), 128>>>(label, aw1, ab1, aw2, ab2,
                                                          aw3, ab3, aw4, ab4, ml, out);
}